// round 3
// baseline (speedup 1.0000x reference)
#include <cuda_runtime.h>
#include <cuda_fp16.h>

// EmbedGraphConv: out[n] = norm_r[n] * sum_{e: dst[e]=n} (embedding[feat[src[e]]] * norm_l[src[e]]) + bias
// Counting-sort edges by dst -> atomic-free warp-per-node aggregation.
// h materialized in FP16 (halves the 410MB L2 gather); accumulation in FP32.

#define NN 50000
#define NE 800000
#define DD 128

// Scratch (device globals: allocation forbidden by harness rules)
__device__ int     g_out_deg[NN];
__device__ int     g_in_deg[NN];
__device__ int     g_offsets[NN];
__device__ int     g_cursor[NN];
__device__ int     g_sorted_src[NE];
__device__ __half2 g_h[(size_t)NN * (DD / 2)];   // 12.8 MB, L2-resident

__global__ void k_hist(const int* __restrict__ src, const int* __restrict__ dst, int e) {
    int i = blockIdx.x * blockDim.x + threadIdx.x;
    if (i < e) {
        atomicAdd(&g_out_deg[src[i]], 1);
        atomicAdd(&g_in_deg[dst[i]], 1);
    }
}

// Exclusive scan of in_deg over NN bins: single block, 1024 threads, chunked.
// Writes both g_offsets (pristine, for k_agg) and g_cursor (consumed by scatter).
__global__ void k_scan(int n) {
    __shared__ int sh[1024];
    int t = threadIdx.x;
    int chunk = (n + 1023) / 1024;
    int lo = t * chunk;
    int hi = min(lo + chunk, n);
    int s = 0;
    for (int i = lo; i < hi; i++) s += g_in_deg[i];
    sh[t] = s;
    __syncthreads();
    for (int off = 1; off < 1024; off <<= 1) {
        int v = (t >= off) ? sh[t - off] : 0;
        __syncthreads();
        sh[t] += v;
        __syncthreads();
    }
    int run = (t == 0) ? 0 : sh[t - 1];
    for (int i = lo; i < hi; i++) {
        g_offsets[i] = run;
        g_cursor[i]  = run;
        run += g_in_deg[i];
    }
}

// Counting-sort scatter: cursor already holds base offset -> one atomic = final slot.
__global__ void k_scatter(const int* __restrict__ src, const int* __restrict__ dst, int e) {
    int i = blockIdx.x * blockDim.x + threadIdx.x;
    if (i < e) {
        int pos = atomicAdd(&g_cursor[dst[i]], 1);
        g_sorted_src[pos] = src[i];
    }
}

// Materialize h[n] = fp16(embedding[feat[n]] * out_deg[n]^{-1/2})
// One thread per float4 (32 threads/node); writes one 8B half4 chunk.
__global__ void k_build_h(const int* __restrict__ feat, const float4* __restrict__ emb, int n) {
    int idx = blockIdx.x * blockDim.x + threadIdx.x;
    if (idx < n * (DD / 4)) {
        int node = idx >> 5;
        int c    = idx & 31;
        float nl = rsqrtf((float)max(g_out_deg[node], 1));
        float4 v = emb[(size_t)feat[node] * 32 + c];
        __half2 a = __floats2half2_rn(v.x * nl, v.y * nl);
        __half2 b = __floats2half2_rn(v.z * nl, v.w * nl);
        g_h[(size_t)idx * 2]     = a;
        g_h[(size_t)idx * 2 + 1] = b;
    }
}

// Warp-per-node aggregation: each lane owns 4 halves (8B) of the 256B row.
__global__ void k_agg(const float4* __restrict__ bias4, float4* __restrict__ out4, int n) {
    int warp = (blockIdx.x * blockDim.x + threadIdx.x) >> 5;
    int lane = threadIdx.x & 31;
    if (warp >= n) return;

    int start = g_offsets[warp];
    int cnt   = g_in_deg[warp];
    const uint2* __restrict__ h2 = reinterpret_cast<const uint2*>(g_h);

    float ax = 0.f, ay = 0.f, az = 0.f, aw = 0.f;
    int i = 0;
    // unroll-by-4: 4 independent rows in flight per warp (deep MLP vs ~250cyc L2)
    for (; i + 3 < cnt; i += 4) {
        int s0 = g_sorted_src[start + i];
        int s1 = g_sorted_src[start + i + 1];
        int s2 = g_sorted_src[start + i + 2];
        int s3 = g_sorted_src[start + i + 3];
        uint2 u0 = h2[(size_t)s0 * 32 + lane];
        uint2 u1 = h2[(size_t)s1 * 32 + lane];
        uint2 u2 = h2[(size_t)s2 * 32 + lane];
        uint2 u3 = h2[(size_t)s3 * 32 + lane];
        #define ACC(u) { \
            float2 f0 = __half22float2(*reinterpret_cast<const __half2*>(&(u).x)); \
            float2 f1 = __half22float2(*reinterpret_cast<const __half2*>(&(u).y)); \
            ax += f0.x; ay += f0.y; az += f1.x; aw += f1.y; }
        ACC(u0) ACC(u1) ACC(u2) ACC(u3)
    }
    for (; i < cnt; i++) {
        int s0 = g_sorted_src[start + i];
        uint2 u0 = h2[(size_t)s0 * 32 + lane];
        ACC(u0)
        #undef ACC
    }

    float nr = rsqrtf((float)max(cnt, 1));
    float4 bv = bias4[lane];
    float4 o;
    o.x = ax * nr + bv.x;
    o.y = ay * nr + bv.y;
    o.z = az * nr + bv.z;
    o.w = aw * nr + bv.w;
    out4[(size_t)warp * 32 + lane] = o;
}

extern "C" void kernel_launch(void* const* d_in, const int* in_sizes, int n_in,
                              void* d_out, int out_size) {
    const int*    feat = (const int*)d_in[0];
    const int*    src  = (const int*)d_in[1];
    const int*    dst  = (const int*)d_in[2];
    const float*  emb  = (const float*)d_in[3];
    const float*  bias = (const float*)d_in[4];
    float*        out  = (float*)d_out;

    int n = in_sizes[0];   // 50000
    int e = in_sizes[1];   // 800000

    // Zero degree arrays via capturable stream memsets (replaces k_zero kernel).
    void* p_out_deg = nullptr;
    void* p_in_deg  = nullptr;
    cudaGetSymbolAddress(&p_out_deg, g_out_deg);
    cudaGetSymbolAddress(&p_in_deg,  g_in_deg);
    cudaMemsetAsync(p_out_deg, 0, (size_t)n * sizeof(int));
    cudaMemsetAsync(p_in_deg,  0, (size_t)n * sizeof(int));

    const int T = 256;
    k_hist   <<<(e + T - 1) / T, T>>>(src, dst, e);
    k_scan   <<<1, 1024>>>(n);
    k_scatter<<<(e + T - 1) / T, T>>>(src, dst, e);
    k_build_h<<<(n * (DD / 4) + T - 1) / T, T>>>(feat, (const float4*)emb, n);
    k_agg    <<<(n * 32 + T - 1) / T, T>>>((const float4*)bias, (float4*)out, n);
}

// round 5
// speedup vs baseline: 1.0041x; 1.0041x over previous
#include <cuda_runtime.h>
#include <cuda_fp16.h>

// EmbedGraphConv: out[n] = norm_r[n] * sum_{e: dst[e]=n} (embedding[feat[src[e]]] * norm_l[src[e]]) + bias
// Counting-sort edges by dst -> atomic-free warp-per-node aggregation.
// h in FP16 (halves the dominant L2 gather); accumulation in FP32.
// R4 resubmit: R4 bench was an infra failure (device busy), no signal obtained.

#define NN 50000
#define NE 800000
#define DD 128

// Scratch (device globals: allocation forbidden by harness rules)
__device__ int     g_out_deg[NN];
__device__ int     g_in_deg[NN];
__device__ int     g_offsets[NN];
__device__ int     g_cursor[NN];
__device__ int     g_sorted_src[NE];
__device__ __half2 g_h[(size_t)NN * (DD / 2)];   // 12.8 MB, L2-resident

__global__ void k_zero(int n) {
    int i = blockIdx.x * blockDim.x + threadIdx.x;
    if (i < n) { g_out_deg[i] = 0; g_in_deg[i] = 0; }
}

__global__ void k_hist(const int* __restrict__ src, const int* __restrict__ dst, int e) {
    int i = blockIdx.x * blockDim.x + threadIdx.x;
    if (i < e) {
        atomicAdd(&g_out_deg[src[i]], 1);
        atomicAdd(&g_in_deg[dst[i]], 1);
    }
}

// Exclusive scan of in_deg over NN bins: single block, 1024 threads, chunked.
// Writes both g_offsets (pristine, for k_agg) and g_cursor (consumed by scatter).
__global__ void k_scan(int n) {
    __shared__ int sh[1024];
    int t = threadIdx.x;
    int chunk = (n + 1023) / 1024;
    int lo = t * chunk;
    int hi = min(lo + chunk, n);
    int s = 0;
    for (int i = lo; i < hi; i++) s += g_in_deg[i];
    sh[t] = s;
    __syncthreads();
    for (int off = 1; off < 1024; off <<= 1) {
        int v = (t >= off) ? sh[t - off] : 0;
        __syncthreads();
        sh[t] += v;
        __syncthreads();
    }
    int run = (t == 0) ? 0 : sh[t - 1];
    for (int i = lo; i < hi; i++) {
        g_offsets[i] = run;
        g_cursor[i]  = run;
        run += g_in_deg[i];
    }
}

// Counting-sort scatter: cursor already holds base offset -> one atomic = final slot.
__global__ void k_scatter(const int* __restrict__ src, const int* __restrict__ dst, int e) {
    int i = blockIdx.x * blockDim.x + threadIdx.x;
    if (i < e) {
        int pos = atomicAdd(&g_cursor[dst[i]], 1);
        g_sorted_src[pos] = src[i];
    }
}

// Materialize h[n] = fp16(embedding[feat[n]] * out_deg[n]^{-1/2})
__global__ void k_build_h(const int* __restrict__ feat, const float4* __restrict__ emb, int n) {
    int idx = blockIdx.x * blockDim.x + threadIdx.x;
    if (idx < n * (DD / 4)) {
        int node = idx >> 5;
        int c    = idx & 31;
        float nl = rsqrtf((float)max(g_out_deg[node], 1));
        float4 v = emb[(size_t)feat[node] * 32 + c];
        __half2 a = __floats2half2_rn(v.x * nl, v.y * nl);
        __half2 b = __floats2half2_rn(v.z * nl, v.w * nl);
        g_h[(size_t)idx * 2]     = a;
        g_h[(size_t)idx * 2 + 1] = b;
    }
}

// Warp-per-node aggregation: each lane owns 4 halves (8B) of the 256B row.
__global__ void k_agg(const float4* __restrict__ bias4, float4* __restrict__ out4, int n) {
    int warp = (blockIdx.x * blockDim.x + threadIdx.x) >> 5;
    int lane = threadIdx.x & 31;
    if (warp >= n) return;

    int start = g_offsets[warp];
    int cnt   = g_in_deg[warp];
    const uint2* __restrict__ h2 = reinterpret_cast<const uint2*>(g_h);

    float ax = 0.f, ay = 0.f, az = 0.f, aw = 0.f;
    int i = 0;
    // unroll-by-4: 4 independent rows in flight per warp
    for (; i + 3 < cnt; i += 4) {
        int s0 = g_sorted_src[start + i];
        int s1 = g_sorted_src[start + i + 1];
        int s2 = g_sorted_src[start + i + 2];
        int s3 = g_sorted_src[start + i + 3];
        uint2 u0 = h2[(size_t)s0 * 32 + lane];
        uint2 u1 = h2[(size_t)s1 * 32 + lane];
        uint2 u2 = h2[(size_t)s2 * 32 + lane];
        uint2 u3 = h2[(size_t)s3 * 32 + lane];
        #define ACC(u) { \
            float2 f0 = __half22float2(*reinterpret_cast<const __half2*>(&(u).x)); \
            float2 f1 = __half22float2(*reinterpret_cast<const __half2*>(&(u).y)); \
            ax += f0.x; ay += f0.y; az += f1.x; aw += f1.y; }
        ACC(u0) ACC(u1) ACC(u2) ACC(u3)
    }
    for (; i < cnt; i++) {
        int s0 = g_sorted_src[start + i];
        uint2 u0 = h2[(size_t)s0 * 32 + lane];
        ACC(u0)
        #undef ACC
    }

    float nr = rsqrtf((float)max(cnt, 1));
    float4 bv = bias4[lane];
    float4 o;
    o.x = ax * nr + bv.x;
    o.y = ay * nr + bv.y;
    o.z = az * nr + bv.z;
    o.w = aw * nr + bv.w;
    out4[(size_t)warp * 32 + lane] = o;
}

extern "C" void kernel_launch(void* const* d_in, const int* in_sizes, int n_in,
                              void* d_out, int out_size) {
    const int*    feat = (const int*)d_in[0];
    const int*    src  = (const int*)d_in[1];
    const int*    dst  = (const int*)d_in[2];
    const float*  emb  = (const float*)d_in[3];
    const float*  bias = (const float*)d_in[4];
    float*        out  = (float*)d_out;

    int n = in_sizes[0];   // 50000
    int e = in_sizes[1];   // 800000

    const int T = 256;
    k_zero   <<<(n + T - 1) / T, T>>>(n);
    k_hist   <<<(e + T - 1) / T, T>>>(src, dst, e);
    k_scan   <<<1, 1024>>>(n);
    k_scatter<<<(e + T - 1) / T, T>>>(src, dst, e);
    k_build_h<<<(n * (DD / 4) + T - 1) / T, T>>>(feat, (const float4*)emb, n);
    k_agg    <<<(n * 32 + T - 1) / T, T>>>((const float4*)bias, (float4*)out, n);
}